// round 12
// baseline (speedup 1.0000x reference)
#include <cuda_runtime.h>
#include <math.h>
#include <float.h>

#define BB 2
#define NN 8192
#define KK 16
#define CC 64
#define BN (BB*NN)

typedef unsigned long long ull;

__device__ __forceinline__ ull pk(float a, float b) {
    ull d; asm("mov.b64 %0,{%1,%2};" : "=l"(d) : "f"(a), "f"(b)); return d;
}
__device__ __forceinline__ void upk(ull s, float& a, float& b) {
    asm("mov.b64 {%0,%1},%2;" : "=f"(a), "=f"(b) : "l"(s));
}
__device__ __forceinline__ ull f2fma(ull a, ull b, ull c) {
    ull d; asm("fma.rn.f32x2 %0,%1,%2,%3;" : "=l"(d) : "l"(a), "l"(b), "l"(c)); return d;
}
__device__ __forceinline__ ull f2add(ull a, ull b) {
    ull d; asm("add.rn.f32x2 %0,%1,%2;" : "=l"(d) : "l"(a), "l"(b)); return d;
}

// sortable-float mapping: exact total order on f32 as u32 (handles negatives)
__device__ __forceinline__ unsigned senc(float d) {
    unsigned u = __float_as_uint(d);
    unsigned mask = ((unsigned)(((int)u) >> 31)) | 0x80000000u;
    return u ^ mask;
}

// scratch (device globals — no runtime allocation)
__device__ ull    g_q2[BN*32];     // (q[row][l], q[row][l+32])
__device__ ull    g_k2[BN*32];
__device__ ull    g_v2[BN*32];
__device__ int    g_idx[BN*KK];
__device__ float4 g_pos4[BN];      // (x, y, z, ||p||^2)
__device__ float4 s_pos4g[BN];     // radius-sorted pos4
__device__ int    s_oidxg[BN];     // sorted position -> original index
__device__ float  g_rbound[BB][64];// radius of first point of each tile

#define TS 512
#define NT (NN/TS)   // 16 tiles
#define QPB 16       // sorted queries per knn block

// ---------------------------------------------------------------------------
// Kernel 0: precompute pos4 with the exact fmaf chain used everywhere.
// ---------------------------------------------------------------------------
__global__ void prep_kernel(const float* __restrict__ pos) {
    int i = blockIdx.x * 256 + threadIdx.x;
    float x = pos[3 * i], y = pos[3 * i + 1], z = pos[3 * i + 2];
    g_pos4[i] = make_float4(x, y, z, fmaf(z, z, fmaf(y, y, x * x)));
}

// ---------------------------------------------------------------------------
// Kernel 0b: radius-sort points (bitonic in smem). Key = (bits(|p|^2), idx);
// |p|^2 >= 0 so raw uint order == float order. Selection downstream is
// order-independent, so sort order only affects pruning efficiency.
// ---------------------------------------------------------------------------
__global__ void __launch_bounds__(1024) sort_kernel() {
    extern __shared__ ull sk[];   // NN keys = 64 KB
    int b = blockIdx.x;
    int tid = threadIdx.x;
    const float4* pb4 = g_pos4 + (size_t)b * NN;
    for (int i = tid; i < NN; i += 1024)
        sk[i] = (((ull)__float_as_uint(pb4[i].w)) << 32) | (unsigned)i;
    __syncthreads();
    for (int k = 2; k <= NN; k <<= 1) {
        for (int j = k >> 1; j > 0; j >>= 1) {
            for (int i = tid; i < NN; i += 1024) {
                int ixj = i ^ j;
                if (ixj > i) {
                    ull a = sk[i], c = sk[ixj];
                    bool up = ((i & k) == 0);
                    if ((a > c) == up) { sk[i] = c; sk[ixj] = a; }
                }
            }
            __syncthreads();
        }
    }
    for (int i = tid; i < NN; i += 1024) {
        int orig = (int)(unsigned)(sk[i] & 0xFFFFFFFFu);
        s_pos4g[(size_t)b * NN + i] = pb4[orig];
        s_oidxg[(size_t)b * NN + i] = orig;
    }
    if (tid < NT) {
        int orig = (int)(unsigned)(sk[tid * TS] & 0xFFFFFFFFu);
        g_rbound[b][tid] = sqrtf(pb4[orig].w);
    }
}

// ---------------------------------------------------------------------------
// Kernel 1: x = feat@emb_w + emb_b ; q/k/v = x@wq/wk/wv.  (unchanged)
// ---------------------------------------------------------------------------
#define PW 4
__global__ void __launch_bounds__(128) proj_kernel(
        const float* __restrict__ feat,
        const float* __restrict__ emb_w, const float* __restrict__ emb_b,
        const float* __restrict__ wq, const float* __restrict__ wk,
        const float* __restrict__ wv) {
    extern __shared__ ull pu[];
    ull* we2 = pu;              // 2048
    ull* wq2 = pu + 2048;
    ull* wk2 = pu + 4096;
    ull* wv2 = pu + 6144;
    ull* Sbase = pu + 8192;     // PW * 576
    ull* ebp = Sbase + PW * 576; // 32

    int tid = threadIdx.x, lane = tid & 31, w = tid >> 5;
    for (int e = tid; e < 2048; e += 128) {
        int j = e >> 5, l2 = e & 31;
        we2[e] = pk(emb_w[j * 64 + l2], emb_w[j * 64 + l2 + 32]);
        wq2[e] = pk(wq[j * 64 + l2],   wq[j * 64 + l2 + 32]);
        wk2[e] = pk(wk[j * 64 + l2],   wk[j * 64 + l2 + 32]);
        wv2[e] = pk(wv[j * 64 + l2],   wv[j * 64 + l2 + 32]);
    }
    if (tid < 32) ebp[tid] = pk(emb_b[tid], emb_b[tid + 32]);

    int rows = (blockIdx.x * PW + w) * 16;
    ull* S = Sbase + w * 576;

#pragma unroll
    for (int rp = 0; rp < 8; rp++) {
        const float* f0 = feat + (size_t)(rows + 2 * rp) * 64;
        const float* f1 = f0 + 64;
        S[lane * 9 + rp]        = pk(f0[lane],      f1[lane]);
        S[(lane + 32) * 9 + rp] = pk(f0[lane + 32], f1[lane + 32]);
    }
    __syncthreads();

    ull xL[8], xH[8];
    {
        float bl, bh;
        upk(ebp[lane], bl, bh);
        ull bl2 = pk(bl, bl), bh2 = pk(bh, bh);
#pragma unroll
        for (int rp = 0; rp < 8; rp++) { xL[rp] = bl2; xH[rp] = bh2; }
    }
#pragma unroll 4
    for (int j = 0; j < 64; j++) {
        ull wp = we2[j * 32 + lane];
        float wl, wh;
        upk(wp, wl, wh);
        ull wl2 = pk(wl, wl), wh2 = pk(wh, wh);
        const ull* s = S + j * 9;
#pragma unroll
        for (int rp = 0; rp < 8; rp++) {
            ull s2 = s[rp];
            xL[rp] = f2fma(s2, wl2, xL[rp]);
            xH[rp] = f2fma(s2, wh2, xH[rp]);
        }
    }
    __syncwarp();
#pragma unroll
    for (int rp = 0; rp < 8; rp++) {
        S[lane * 9 + rp]        = xL[rp];
        S[(lane + 32) * 9 + rp] = xH[rp];
    }
    __syncwarp();

    ull qL[8], qH[8], kL[8], kH[8], vL[8], vH[8];
#pragma unroll
    for (int rp = 0; rp < 8; rp++) {
        qL[rp] = qH[rp] = kL[rp] = kH[rp] = vL[rp] = vH[rp] = 0ull;
    }
#pragma unroll 2
    for (int j = 0; j < 64; j++) {
        float a, b;
        upk(wq2[j * 32 + lane], a, b);
        ull wql = pk(a, a), wqh = pk(b, b);
        upk(wk2[j * 32 + lane], a, b);
        ull wkl = pk(a, a), wkh = pk(b, b);
        upk(wv2[j * 32 + lane], a, b);
        ull wvl = pk(a, a), wvh = pk(b, b);
        const ull* s = S + j * 9;
#pragma unroll
        for (int rp = 0; rp < 8; rp++) {
            ull s2 = s[rp];
            qL[rp] = f2fma(s2, wql, qL[rp]);
            qH[rp] = f2fma(s2, wqh, qH[rp]);
            kL[rp] = f2fma(s2, wkl, kL[rp]);
            kH[rp] = f2fma(s2, wkh, kH[rp]);
            vL[rp] = f2fma(s2, wvl, vL[rp]);
            vH[rp] = f2fma(s2, wvh, vH[rp]);
        }
    }

#pragma unroll
    for (int rp = 0; rp < 8; rp++) {
        size_t r0 = (size_t)(rows + 2 * rp) * 32 + lane;
        size_t r1 = r0 + 32;
        float a0, a1, b0, b1;
        upk(qL[rp], a0, a1); upk(qH[rp], b0, b1);
        g_q2[r0] = pk(a0, b0); g_q2[r1] = pk(a1, b1);
        upk(kL[rp], a0, a1); upk(kH[rp], b0, b1);
        g_k2[r0] = pk(a0, b0); g_k2[r1] = pk(a1, b1);
        upk(vL[rp], a0, a1); upk(vH[rp], b0, b1);
        g_v2[r0] = pk(a0, b0); g_v2[r1] = pk(a1, b1);
    }
}

// ---------------------------------------------------------------------------
// Kernel 2: KNN — radius-band pruned scan over sorted points.
// 16 radius-consecutive queries per block (2 per warp). Tiles of 512 scanned
// outward from the home tile; block stops when every warp's unscanned radius
// gap satisfies gap^2 >= theta*1.0001 (reverse triangle inequality, slack
// covers float rounding). Selection machinery (u64-key flush) byte-identical
// to the validated R9 version; it is order-independent, so pruned/reordered
// enumeration yields the exact same top-16 set.
// ---------------------------------------------------------------------------
#define KW 8
#define FSLOTS 64

__device__ __noinline__ void knn_flush(ull* kd, int& bc, float& theta, int lane) {
    int n = 16 + bc;
    ull k0 = (lane < n) ? kd[lane] : ~0ull;
    ull k1 = (lane + 32 < n) ? kd[lane + 32] : ~0ull;
    int r0 = 0, r1 = 0;
    for (int j = 0; j < n; j++) {
        ull kj = kd[j];
        r0 += (kj < k0);
        r1 += (kj < k1);
    }
    __syncwarp();
    if (r0 < 16) kd[r0] = k0;
    if (r1 < 16) kd[r1] = k1;
    __syncwarp();
    unsigned hi = (unsigned)(kd[15] >> 32);
    unsigned u = (hi & 0x80000000u) ? (hi ^ 0x80000000u) : ~hi;
    theta = __uint_as_float(u);
    bc = 0;
}

__global__ void __launch_bounds__(256) knn_kernel() {
    extern __shared__ ull ku[];
    float4* tile = (float4*)ku;                 // TS float4 = 1024 ull
    ull*    kbuf = ku + 1024;                   // 16*64 = 1024 ull
    int*    tidx = (int*)(ku + 2048);           // TS ints = 256 ull
    int*    flg  = (int*)(ku + 2048 + 256);     // 2 ints

    int tid = threadIdx.x, lane = tid & 31, w = tid >> 5;
    int b = blockIdx.y;
    int p0 = blockIdx.x * QPB + 2 * w;
    int p1 = p0 + 1;
    const float4* sp = s_pos4g + (size_t)b * NN;
    const int*   soi = s_oidxg + (size_t)b * NN;
    float4 qv0 = sp[p0], qv1 = sp[p1];
    float rq0 = sqrtf(qv0.w), rq1 = sqrtf(qv1.w);
    int oq0 = soi[p0], oq1 = soi[p1];

    ull* kd0 = kbuf + (w * 2 + 0) * FSLOTS;
    ull* kd1 = kbuf + (w * 2 + 1) * FSLOTS;
    if (lane < 16) {
        kd0[lane] = (((ull)0xFF7FFFFFu) << 32) | (unsigned)lane;
        kd1[lane] = (((ull)0xFF7FFFFFu) << 32) | (unsigned)lane;
    }
    __syncwarp();

    float th0 = FLT_MAX, th1 = FLT_MAX;
    int bc0 = 0, bc1 = 0;
    int h = (blockIdx.x * QPB) / TS;

    // ---- home tile: load, prime theta from first 32, scan the rest ----
    for (int i = tid; i < TS; i += 256) {
        tile[i] = sp[h * TS + i];
        tidx[i] = soi[h * TS + i];
    }
    __syncthreads();
    {
        float4 c = tile[lane];
        float dot0 = fmaf(qv0.z, c.z, fmaf(qv0.y, c.y, qv0.x * c.x));
        float dot1 = fmaf(qv1.z, c.z, fmaf(qv1.y, c.y, qv1.x * c.x));
        float d20 = fmaf(-2.f, dot0, qv0.w + c.w);
        float d21 = fmaf(-2.f, dot1, qv1.w + c.w);
        int oi = tidx[lane];
        kd0[16 + lane] = (((ull)senc(d20)) << 32) | (unsigned)oi;
        kd1[16 + lane] = (((ull)senc(d21)) << 32) | (unsigned)oi;
        __syncwarp();
        bc0 = 32; knn_flush(kd0, bc0, th0, lane);
        bc1 = 32; knn_flush(kd1, bc1, th1, lane);
    }
    for (int s = 1; s < TS / 32; s++) {
        float4 c = tile[s * 32 + lane];
        float dot0 = fmaf(qv0.z, c.z, fmaf(qv0.y, c.y, qv0.x * c.x));
        float dot1 = fmaf(qv1.z, c.z, fmaf(qv1.y, c.y, qv1.x * c.x));
        float d20 = fmaf(-2.f, dot0, qv0.w + c.w);
        float d21 = fmaf(-2.f, dot1, qv1.w + c.w);
        bool a0 = d20 < th0;
        bool a1 = d21 < th1;
        if (__ballot_sync(0xffffffffu, a0 | a1)) {
            if (bc0 > 16) { knn_flush(kd0, bc0, th0, lane); a0 = d20 < th0; }
            if (bc1 > 16) { knn_flush(kd1, bc1, th1, lane); a1 = d21 < th1; }
            unsigned m0 = __ballot_sync(0xffffffffu, a0);
            unsigned m1 = __ballot_sync(0xffffffffu, a1);
            int oi = tidx[s * 32 + lane];
            if (m0) {
                int off = __popc(m0 & ((1u << lane) - 1u));
                if (a0) kd0[16 + bc0 + off] = (((ull)senc(d20)) << 32) | (unsigned)oi;
                bc0 += __popc(m0);
            }
            if (m1) {
                int off = __popc(m1 & ((1u << lane) - 1u));
                if (a1) kd1[16 + bc1 + off] = (((ull)senc(d21)) << 32) | (unsigned)oi;
                bc1 += __popc(m1);
            }
        }
    }

    // ---- outward expansion with radius-gap termination ----
    int lo = h, hi = h, toggle = 0;
    while (true) {
        bool ndn = false, nup = false;
        if (lo > 0) {
            float rb = g_rbound[b][lo];
            float g0 = rq0 - rb, g1 = rq1 - rb;
            if (!(g0 > 0.f && g0 * g0 >= th0 * 1.0001f)) ndn = true;
            if (!(g1 > 0.f && g1 * g1 >= th1 * 1.0001f)) ndn = true;
        }
        if (hi < NT - 1) {
            float ra = g_rbound[b][hi + 1];
            float g0 = ra - rq0, g1 = ra - rq1;
            if (!(g0 > 0.f && g0 * g0 >= th0 * 1.0001f)) nup = true;
            if (!(g1 > 0.f && g1 * g1 >= th1 * 1.0001f)) nup = true;
        }
        __syncthreads();
        if (tid < 2) flg[tid] = 0;
        __syncthreads();
        if (lane == 0) {
            if (ndn) atomicOr(&flg[0], 1);
            if (nup) atomicOr(&flg[1], 1);
        }
        __syncthreads();
        int fdn = flg[0], fup = flg[1];
        if (!fdn && !fup) break;
        int t;
        if (fup && (!fdn || toggle == 0)) { t = ++hi; toggle = 1; }
        else                              { t = --lo; toggle = 0; }

        for (int i = tid; i < TS; i += 256) {
            tile[i] = sp[t * TS + i];
            tidx[i] = soi[t * TS + i];
        }
        __syncthreads();
        for (int s = 0; s < TS / 32; s++) {
            float4 c = tile[s * 32 + lane];
            float dot0 = fmaf(qv0.z, c.z, fmaf(qv0.y, c.y, qv0.x * c.x));
            float dot1 = fmaf(qv1.z, c.z, fmaf(qv1.y, c.y, qv1.x * c.x));
            float d20 = fmaf(-2.f, dot0, qv0.w + c.w);
            float d21 = fmaf(-2.f, dot1, qv1.w + c.w);
            bool a0 = d20 < th0;
            bool a1 = d21 < th1;
            if (__ballot_sync(0xffffffffu, a0 | a1)) {
                if (bc0 > 16) { knn_flush(kd0, bc0, th0, lane); a0 = d20 < th0; }
                if (bc1 > 16) { knn_flush(kd1, bc1, th1, lane); a1 = d21 < th1; }
                unsigned m0 = __ballot_sync(0xffffffffu, a0);
                unsigned m1 = __ballot_sync(0xffffffffu, a1);
                int oi = tidx[s * 32 + lane];
                if (m0) {
                    int off = __popc(m0 & ((1u << lane) - 1u));
                    if (a0) kd0[16 + bc0 + off] = (((ull)senc(d20)) << 32) | (unsigned)oi;
                    bc0 += __popc(m0);
                }
                if (m1) {
                    int off = __popc(m1 & ((1u << lane) - 1u));
                    if (a1) kd1[16 + bc1 + off] = (((ull)senc(d21)) << 32) | (unsigned)oi;
                    bc1 += __popc(m1);
                }
            }
        }
    }
    if (bc0 > 0) knn_flush(kd0, bc0, th0, lane);
    if (bc1 > 0) knn_flush(kd1, bc1, th1, lane);
    if (lane < 16) {
        g_idx[((size_t)b * NN + oq0) * KK + lane] = (int)(unsigned)(kd0[lane] & 0xFFFFFFFFu);
        g_idx[((size_t)b * NN + oq1) * KK + lane] = (int)(unsigned)(kd1[lane] & 0xFFFFFFFFu);
    }
}

// ---------------------------------------------------------------------------
// Kernel 3: fused posenc + attn MLPs + softmax + combine + out projection.
// (exact R9 version: AQ=8, smem ulonglong2 weights; measured 165-166 us)
// ---------------------------------------------------------------------------
#define AQ 8
#define SQSTRIDE 640

__device__ __forceinline__ void mv16x64(const ull* __restrict__ Sq,
                                        const ulonglong2* __restrict__ w4, int l,
                                        ull aL[8], ull aH[8]) {
#pragma unroll
    for (int kp = 0; kp < 8; kp++) { aL[kp] = 0ull; aH[kp] = 0ull; }
#pragma unroll 4
    for (int jp = 0; jp < 32; jp++) {
        ulonglong2 wpp = w4[jp * 32 + l];
        {
            float wl, wh;
            upk(wpp.x, wl, wh);
            ull wl2 = pk(wl, wl), wh2 = pk(wh, wh);
            const ulonglong2* s = (const ulonglong2*)(Sq + (2 * jp) * 10);
#pragma unroll
            for (int kp2 = 0; kp2 < 4; kp2++) {
                ulonglong2 sv = s[kp2];
                aL[2 * kp2]     = f2fma(sv.x, wl2, aL[2 * kp2]);
                aH[2 * kp2]     = f2fma(sv.x, wh2, aH[2 * kp2]);
                aL[2 * kp2 + 1] = f2fma(sv.y, wl2, aL[2 * kp2 + 1]);
                aH[2 * kp2 + 1] = f2fma(sv.y, wh2, aH[2 * kp2 + 1]);
            }
        }
        {
            float wl, wh;
            upk(wpp.y, wl, wh);
            ull wl2 = pk(wl, wl), wh2 = pk(wh, wh);
            const ulonglong2* s = (const ulonglong2*)(Sq + (2 * jp + 1) * 10);
#pragma unroll
            for (int kp2 = 0; kp2 < 4; kp2++) {
                ulonglong2 sv = s[kp2];
                aL[2 * kp2]     = f2fma(sv.x, wl2, aL[2 * kp2]);
                aH[2 * kp2]     = f2fma(sv.x, wh2, aH[2 * kp2]);
                aL[2 * kp2 + 1] = f2fma(sv.y, wl2, aL[2 * kp2 + 1]);
                aH[2 * kp2 + 1] = f2fma(sv.y, wh2, aH[2 * kp2 + 1]);
            }
        }
    }
}

__global__ void __launch_bounds__(256) attn_kernel(
        const float* __restrict__ feat,
        const float* __restrict__ pe_w1, const float* __restrict__ pe_b1,
        const float* __restrict__ pe_w2, const float* __restrict__ pe_b2,
        const float* __restrict__ at_w1, const float* __restrict__ at_b1,
        const float* __restrict__ at_w2, const float* __restrict__ at_b2,
        const float* __restrict__ out_w, const float* __restrict__ out_b,
        float* __restrict__ out) {
    extern __shared__ ull smu[];
    ulonglong2* w4_pe2 = (ulonglong2*)smu;           // 1024 u2 (2048 ull)
    ulonglong2* w4_at1 = (ulonglong2*)(smu + 2048);
    ulonglong2* w4_at2 = (ulonglong2*)(smu + 4096);
    ull* Sp2    = smu + 6144;            // AQ*640
    float* s_pe1 = (float*)(Sp2 + AQ * SQSTRIDE);  // 192
    float* s_b   = s_pe1 + 192;          // 320
    float* relb  = s_b + 320;            // AQ*64
    float* resb  = relb + AQ * 64;       // AQ*64
    int*   idxb  = (int*)(resb + AQ * 64);  // AQ*16

    int tid = threadIdx.x;
    for (int e = tid; e < 1024; e += 256) {
        int jp = e >> 5, l2 = e & 31;
        int j0 = 2 * jp, j1 = 2 * jp + 1;
        w4_pe2[e] = make_ulonglong2(pk(pe_w2[j0 * 64 + l2], pe_w2[j0 * 64 + l2 + 32]),
                                    pk(pe_w2[j1 * 64 + l2], pe_w2[j1 * 64 + l2 + 32]));
        w4_at1[e] = make_ulonglong2(pk(at_w1[j0 * 64 + l2], at_w1[j0 * 64 + l2 + 32]),
                                    pk(at_w1[j1 * 64 + l2], at_w1[j1 * 64 + l2 + 32]));
        w4_at2[e] = make_ulonglong2(pk(at_w2[j0 * 64 + l2], at_w2[j0 * 64 + l2 + 32]),
                                    pk(at_w2[j1 * 64 + l2], at_w2[j1 * 64 + l2 + 32]));
    }
    if (tid < 192) s_pe1[tid] = pe_w1[tid];
    if (tid < 64) {
        s_b[tid]       = pe_b1[tid];
        s_b[64 + tid]  = pe_b2[tid];
        s_b[128 + tid] = at_b1[tid];
        s_b[192 + tid] = at_b2[tid];
        s_b[256 + tid] = out_b[tid];
    }

    int wid = tid >> 5;
    int l   = tid & 31;
    int g   = blockIdx.x * AQ + wid;
    int bbase = g & ~(NN - 1);

    float q_lo, q_hi;
    upk(g_q2[(size_t)g * 32 + l], q_lo, q_hi);

    if (l < KK) {
        int ii = g_idx[(size_t)g * KK + l];
        idxb[wid * KK + l] = ii;
        float4 np = g_pos4[bbase + ii];
        float4 qp = g_pos4[g];
        relb[(wid * KK + l) * 4 + 0] = np.x - qp.x;
        relb[(wid * KK + l) * 4 + 1] = np.y - qp.y;
        relb[(wid * KK + l) * 4 + 2] = np.z - qp.z;
    }
    __syncthreads();

    ull* Sq = Sp2 + wid * SQSTRIDE;

    // Stage A: pe1 = relu(rel @ pe_w1 + pe_b1)
    {
        float w0l = s_pe1[l],      w1l = s_pe1[64 + l],  w2l = s_pe1[128 + l];
        float w0h = s_pe1[l + 32], w1h = s_pe1[96 + l],  w2h = s_pe1[160 + l];
        float b1l = s_b[l], b1h = s_b[l + 32];
#pragma unroll
        for (int kp = 0; kp < 8; kp++) {
            const float* ra = relb + (wid * KK + 2 * kp) * 4;
            const float* rb = ra + 4;
            float pa = fmaxf(fmaf(ra[2], w2l, fmaf(ra[1], w1l, fmaf(ra[0], w0l, b1l))), 0.f);
            float pb = fmaxf(fmaf(rb[2], w2l, fmaf(rb[1], w1l, fmaf(rb[0], w0l, b1l))), 0.f);
            Sq[l * 10 + kp] = pk(pa, pb);
            float qa = fmaxf(fmaf(ra[2], w2h, fmaf(ra[1], w1h, fmaf(ra[0], w0h, b1h))), 0.f);
            float qb = fmaxf(fmaf(rb[2], w2h, fmaf(rb[1], w1h, fmaf(rb[0], w0h, b1h))), 0.f);
            Sq[(l + 32) * 10 + kp] = pk(qa, qb);
        }
    }
    __syncwarp();

    // Stage B: posenc = pe1 @ pe_w2 + pe_b2
    ull penL[8], penH[8];
    mv16x64(Sq, w4_pe2, l, penL, penH);
    {
        ull b2l = pk(s_b[64 + l], s_b[64 + l]);
        ull b2h = pk(s_b[64 + l + 32], s_b[64 + l + 32]);
#pragma unroll
        for (int kp = 0; kp < 8; kp++) {
            penL[kp] = f2add(penL[kp], b2l);
            penH[kp] = f2add(penH[kp], b2h);
        }
    }
    __syncwarp();

    // Stage C: h = q - k_feat + posenc
#pragma unroll
    for (int kp = 0; kp < 8; kp++) {
        int i0 = idxb[wid * KK + 2 * kp];
        int i1 = idxb[wid * KK + 2 * kp + 1];
        float k0l, k0h, k1l, k1h;
        upk(g_k2[(size_t)(bbase + i0) * 32 + l], k0l, k0h);
        upk(g_k2[(size_t)(bbase + i1) * 32 + l], k1l, k1h);
        float p0, p1;
        upk(penL[kp], p0, p1);
        Sq[l * 10 + kp] = pk(q_lo - k0l + p0, q_lo - k1l + p1);
        upk(penH[kp], p0, p1);
        Sq[(l + 32) * 10 + kp] = pk(q_hi - k0h + p0, q_hi - k1h + p1);
    }
    __syncwarp();

    // Stage D: a1 = relu(h @ at_w1 + at_b1)
    ull aL[8], aH[8];
    mv16x64(Sq, w4_at1, l, aL, aH);
    __syncwarp();
    {
        float bl = s_b[128 + l], bh = s_b[128 + l + 32];
#pragma unroll
        for (int kp = 0; kp < 8; kp++) {
            float x, y;
            upk(aL[kp], x, y);
            Sq[l * 10 + kp] = pk(fmaxf(x + bl, 0.f), fmaxf(y + bl, 0.f));
            upk(aH[kp], x, y);
            Sq[(l + 32) * 10 + kp] = pk(fmaxf(x + bh, 0.f), fmaxf(y + bh, 0.f));
        }
    }
    __syncwarp();

    // Stage E: logits = (a1 @ at_w2 + at_b2) / 8
    mv16x64(Sq, w4_at2, l, aL, aH);
    float el[KK], eh[KK];
    {
        float bl = s_b[192 + l], bh = s_b[192 + l + 32];
#pragma unroll
        for (int kp = 0; kp < 8; kp++) {
            float x, y;
            upk(aL[kp], x, y);
            el[2 * kp] = (x + bl) * 0.125f; el[2 * kp + 1] = (y + bl) * 0.125f;
            upk(aH[kp], x, y);
            eh[2 * kp] = (x + bh) * 0.125f; eh[2 * kp + 1] = (y + bh) * 0.125f;
        }
    }

    // softmax over K per channel + combine with (v + posenc)
    float ml = el[0], mh = eh[0];
#pragma unroll
    for (int k = 1; k < KK; k++) { ml = fmaxf(ml, el[k]); mh = fmaxf(mh, eh[k]); }
    float sl = 0.f, sh = 0.f;
#pragma unroll
    for (int k = 0; k < KK; k++) {
        el[k] = __expf(el[k] - ml); sl += el[k];
        eh[k] = __expf(eh[k] - mh); sh += eh[k];
    }
    float il = 1.f / sl, ih = 1.f / sh;
    float res_lo = 0.f, res_hi = 0.f;
#pragma unroll
    for (int kp = 0; kp < 8; kp++) {
        int i0 = idxb[wid * KK + 2 * kp];
        int i1 = idxb[wid * KK + 2 * kp + 1];
        float v0l, v0h, v1l, v1h;
        upk(g_v2[(size_t)(bbase + i0) * 32 + l], v0l, v0h);
        upk(g_v2[(size_t)(bbase + i1) * 32 + l], v1l, v1h);
        float p0, p1;
        upk(penL[kp], p0, p1);
        res_lo = fmaf(el[2 * kp] * il,     v0l + p0, res_lo);
        res_lo = fmaf(el[2 * kp + 1] * il, v1l + p1, res_lo);
        upk(penH[kp], p0, p1);
        res_hi = fmaf(eh[2 * kp] * ih,     v0h + p0, res_hi);
        res_hi = fmaf(eh[2 * kp + 1] * ih, v1h + p1, res_hi);
    }
    resb[wid * CC + l] = res_lo;
    resb[wid * CC + l + 32] = res_hi;
    __syncwarp();

    // final: out = res @ out_w + out_b + features (out_w via L1)
    {
        float ol = s_b[256 + l], oh = s_b[256 + l + 32];
#pragma unroll 4
        for (int j = 0; j < 64; j++) {
            float rj = resb[wid * CC + j];
            ol = fmaf(rj, __ldg(&out_w[j * 64 + l]), ol);
            oh = fmaf(rj, __ldg(&out_w[j * 64 + l + 32]), oh);
        }
        out[(size_t)g * CC + l]      = ol + feat[(size_t)g * CC + l];
        out[(size_t)g * CC + l + 32] = oh + feat[(size_t)g * CC + l + 32];
    }
}

// ---------------------------------------------------------------------------
extern "C" void kernel_launch(void* const* d_in, const int* in_sizes, int n_in,
                              void* d_out, int out_size) {
    const float* pos   = (const float*)d_in[0];
    const float* feat  = (const float*)d_in[1];
    const float* emb_w = (const float*)d_in[2];
    const float* emb_b = (const float*)d_in[3];
    const float* wq    = (const float*)d_in[4];
    const float* wk    = (const float*)d_in[5];
    const float* wv    = (const float*)d_in[6];
    const float* pe_w1 = (const float*)d_in[7];
    const float* pe_b1 = (const float*)d_in[8];
    const float* pe_w2 = (const float*)d_in[9];
    const float* pe_b2 = (const float*)d_in[10];
    const float* at_w1 = (const float*)d_in[11];
    const float* at_b1 = (const float*)d_in[12];
    const float* at_w2 = (const float*)d_in[13];
    const float* at_b2 = (const float*)d_in[14];
    const float* out_w = (const float*)d_in[15];
    const float* out_b = (const float*)d_in[16];
    float* out = (float*)d_out;

    int sort_smem = NN * 8;
    int proj_smem = (8192 + PW * 576 + 32) * 8;
    int knn_smem  = (2048 + 256 + 2) * 8;
    int attn_smem = (6144 + AQ * SQSTRIDE) * 8
                  + (192 + 320 + AQ * 64 * 2) * 4 + AQ * KK * 4;
    cudaFuncSetAttribute(sort_kernel, cudaFuncAttributeMaxDynamicSharedMemorySize, sort_smem);
    cudaFuncSetAttribute(proj_kernel, cudaFuncAttributeMaxDynamicSharedMemorySize, proj_smem);
    cudaFuncSetAttribute(knn_kernel, cudaFuncAttributeMaxDynamicSharedMemorySize, knn_smem);
    cudaFuncSetAttribute(attn_kernel, cudaFuncAttributeMaxDynamicSharedMemorySize, attn_smem);

    prep_kernel<<<BN / 256, 256>>>(pos);
    sort_kernel<<<BB, 1024, sort_smem>>>();
    proj_kernel<<<BN / (PW * 16), 128, proj_smem>>>(feat, emb_w, emb_b, wq, wk, wv);
    knn_kernel<<<dim3(NN / QPB, BB), 256, knn_smem>>>();
    attn_kernel<<<BN / AQ, 256, attn_smem>>>(feat, pe_w1, pe_b1, pe_w2, pe_b2,
                                             at_w1, at_b1, at_w2, at_b2, out_w, out_b, out);
}

// round 13
// speedup vs baseline: 1.2008x; 1.2008x over previous
#include <cuda_runtime.h>
#include <math.h>
#include <float.h>

#define BB 2
#define NN 8192
#define KK 16
#define CC 64
#define BN (BB*NN)

typedef unsigned long long ull;

__device__ __forceinline__ ull pk(float a, float b) {
    ull d; asm("mov.b64 %0,{%1,%2};" : "=l"(d) : "f"(a), "f"(b)); return d;
}
__device__ __forceinline__ void upk(ull s, float& a, float& b) {
    asm("mov.b64 {%0,%1},%2;" : "=f"(a), "=f"(b) : "l"(s));
}
__device__ __forceinline__ ull f2fma(ull a, ull b, ull c) {
    ull d; asm("fma.rn.f32x2 %0,%1,%2,%3;" : "=l"(d) : "l"(a), "l"(b), "l"(c)); return d;
}
__device__ __forceinline__ ull f2add(ull a, ull b) {
    ull d; asm("add.rn.f32x2 %0,%1,%2;" : "=l"(d) : "l"(a), "l"(b)); return d;
}

// sortable-float mapping: exact total order on f32 as u32 (handles negatives)
__device__ __forceinline__ unsigned senc(float d) {
    unsigned u = __float_as_uint(d);
    unsigned mask = ((unsigned)(((int)u) >> 31)) | 0x80000000u;
    return u ^ mask;
}

// scratch (device globals — no runtime allocation)
__device__ ull    g_q2[BN*32];     // (q[row][l], q[row][l+32])
__device__ ull    g_k2[BN*32];
__device__ ull    g_v2[BN*32];
__device__ int    g_idx[BN*KK];
__device__ float4 g_pos4[BN];      // (x, y, z, ||p||^2)
__device__ float4 s_pos4g[BN];     // radius-binned pos4
__device__ int    s_oidxg[BN];     // binned position -> original index

#define TS 256
#define NT (NN/TS)   // 32 tiles
#define QPB 16       // binned queries per knn block
#define NBINS 512

__device__ unsigned g_hist[BB][NBINS];
__device__ unsigned g_curs[BB][NBINS];
__device__ unsigned g_w2min[BB], g_w2max[BB];
__device__ float    g_maxbelow[BB][NT + 1];  // max radius over positions < t*TS
__device__ float    g_minabove[BB][NT + 1];  // min radius over positions >= t*TS

// ---------------------------------------------------------------------------
// Kernel 0a: reset accumulators (must run every launch; graph-replayed).
// ---------------------------------------------------------------------------
__global__ void init_kernel() {
    int b = blockIdx.x, tid = threadIdx.x;
    g_hist[b][tid] = 0;
    if (tid == 0) { g_w2min[b] = 0xFFFFFFFFu; g_w2max[b] = 0u; }
}

// ---------------------------------------------------------------------------
// Kernel 0b: pos4 (exact fmaf chain) + per-batch min/max of ||p||^2 bits.
// Nonnegative floats: uint bit order == float order.
// ---------------------------------------------------------------------------
__global__ void prep_kernel(const float* __restrict__ pos) {
    __shared__ unsigned smin[8], smax[8];
    int i = blockIdx.x * 256 + threadIdx.x;
    int b = i / NN;
    float x = pos[3 * i], y = pos[3 * i + 1], z = pos[3 * i + 2];
    float w = fmaf(z, z, fmaf(y, y, x * x));
    g_pos4[i] = make_float4(x, y, z, w);
    unsigned wb = __float_as_uint(w);
    // warp reduce
#pragma unroll
    for (int d = 16; d > 0; d >>= 1) {
        unsigned o = __shfl_down_sync(0xffffffffu, wb, d);
        // track both min and max with two vars
        // (recompute: keep two registers)
        (void)o;
    }
    // simpler: two-pass warp reductions
    unsigned mn = wb, mx = wb;
#pragma unroll
    for (int d = 16; d > 0; d >>= 1) {
        mn = min(mn, __shfl_down_sync(0xffffffffu, mn, d));
        mx = max(mx, __shfl_down_sync(0xffffffffu, mx, d));
    }
    int lane = threadIdx.x & 31, wrp = threadIdx.x >> 5;
    if (lane == 0) { smin[wrp] = mn; smax[wrp] = mx; }
    __syncthreads();
    if (threadIdx.x == 0) {
        unsigned bmn = smin[0], bmx = smax[0];
        for (int k = 1; k < 8; k++) { bmn = min(bmn, smin[k]); bmx = max(bmx, smax[k]); }
        atomicMin(&g_w2min[b], bmn);
        atomicMax(&g_w2max[b], bmx);
    }
}

// ---------------------------------------------------------------------------
// Kernel 0c: histogram of radius bins.
// ---------------------------------------------------------------------------
__device__ __forceinline__ int rbin(float r, float rmin, float inv) {
    int bin = (int)((r - rmin) * inv);
    return min(max(bin, 0), NBINS - 1);
}

__global__ void hist_kernel() {
    int i = blockIdx.x * 256 + threadIdx.x;
    int b = i / NN;
    float rmin = sqrtf(__uint_as_float(g_w2min[b]));
    float rmax = sqrtf(__uint_as_float(g_w2max[b]));
    float inv = (rmax > rmin) ? (float)NBINS / (rmax - rmin) : 0.f;
    float r = sqrtf(g_pos4[i].w);
    atomicAdd(&g_hist[b][rbin(r, rmin, inv)], 1u);
}

// Kernel 0d: exclusive prefix sum of hist -> cursors.
__global__ void scan_kernel() {
    __shared__ unsigned sh[NBINS];
    int b = blockIdx.x, tid = threadIdx.x;
    sh[tid] = g_hist[b][tid];
    __syncthreads();
    for (int off = 1; off < NBINS; off <<= 1) {
        unsigned v = (tid >= off) ? sh[tid - off] : 0u;
        __syncthreads();
        sh[tid] += v;
        __syncthreads();
    }
    g_curs[b][tid] = sh[tid] - g_hist[b][tid];  // exclusive
}

// Kernel 0e: scatter points into bin order (within-bin order arbitrary —
// selection downstream is order-independent, bounds computed from actual data).
__global__ void scatter_kernel() {
    int i = blockIdx.x * 256 + threadIdx.x;
    int b = i / NN;
    float rmin = sqrtf(__uint_as_float(g_w2min[b]));
    float rmax = sqrtf(__uint_as_float(g_w2max[b]));
    float inv = (rmax > rmin) ? (float)NBINS / (rmax - rmin) : 0.f;
    float4 p = g_pos4[i];
    float r = sqrtf(p.w);
    unsigned pos = atomicAdd(&g_curs[b][rbin(r, rmin, inv)], 1u);
    s_pos4g[(size_t)b * NN + pos] = p;
    s_oidxg[(size_t)b * NN + pos] = i - b * NN;
}

// Kernel 0f: exact per-tile radius min/max -> prefix max-below / suffix min-above.
__global__ void __launch_bounds__(1024) bounds_kernel() {
    __shared__ unsigned tmin[NT], tmax[NT];
    int b = blockIdx.x, tid = threadIdx.x;
    if (tid < NT) { tmin[tid] = 0xFFFFFFFFu; tmax[tid] = 0u; }
    __syncthreads();
    // each thread handles 8 consecutive positions (within one tile: 256%8==0)
    unsigned mn = 0xFFFFFFFFu, mx = 0u;
    int base = tid * 8;
    int t = base / TS;
#pragma unroll
    for (int e = 0; e < 8; e++) {
        unsigned wb = __float_as_uint(s_pos4g[(size_t)b * NN + base + e].w);
        mn = min(mn, wb);
        mx = max(mx, wb);
    }
    atomicMin(&tmin[t], mn);
    atomicMax(&tmax[t], mx);
    __syncthreads();
    if (tid == 0) {
        float runmax = 0.f;
        for (int k = 0; k <= NT; k++) {
            g_maxbelow[b][k] = (k == 0) ? 0.f : runmax;
            if (k < NT) runmax = fmaxf(runmax, sqrtf(__uint_as_float(tmax[k])));
        }
        float runmin = FLT_MAX;
        for (int k = NT; k >= 0; k--) {
            g_minabove[b][k] = runmin;
            if (k > 0) runmin = fminf(runmin, sqrtf(__uint_as_float(tmin[k - 1])));
        }
    }
}

// ---------------------------------------------------------------------------
// Kernel 1: x = feat@emb_w + emb_b ; q/k/v = x@wq/wk/wv.  (unchanged)
// ---------------------------------------------------------------------------
#define PW 4
__global__ void __launch_bounds__(128) proj_kernel(
        const float* __restrict__ feat,
        const float* __restrict__ emb_w, const float* __restrict__ emb_b,
        const float* __restrict__ wq, const float* __restrict__ wk,
        const float* __restrict__ wv) {
    extern __shared__ ull pu[];
    ull* we2 = pu;              // 2048
    ull* wq2 = pu + 2048;
    ull* wk2 = pu + 4096;
    ull* wv2 = pu + 6144;
    ull* Sbase = pu + 8192;     // PW * 576
    ull* ebp = Sbase + PW * 576; // 32

    int tid = threadIdx.x, lane = tid & 31, w = tid >> 5;
    for (int e = tid; e < 2048; e += 128) {
        int j = e >> 5, l2 = e & 31;
        we2[e] = pk(emb_w[j * 64 + l2], emb_w[j * 64 + l2 + 32]);
        wq2[e] = pk(wq[j * 64 + l2],   wq[j * 64 + l2 + 32]);
        wk2[e] = pk(wk[j * 64 + l2],   wk[j * 64 + l2 + 32]);
        wv2[e] = pk(wv[j * 64 + l2],   wv[j * 64 + l2 + 32]);
    }
    if (tid < 32) ebp[tid] = pk(emb_b[tid], emb_b[tid + 32]);

    int rows = (blockIdx.x * PW + w) * 16;
    ull* S = Sbase + w * 576;

#pragma unroll
    for (int rp = 0; rp < 8; rp++) {
        const float* f0 = feat + (size_t)(rows + 2 * rp) * 64;
        const float* f1 = f0 + 64;
        S[lane * 9 + rp]        = pk(f0[lane],      f1[lane]);
        S[(lane + 32) * 9 + rp] = pk(f0[lane + 32], f1[lane + 32]);
    }
    __syncthreads();

    ull xL[8], xH[8];
    {
        float bl, bh;
        upk(ebp[lane], bl, bh);
        ull bl2 = pk(bl, bl), bh2 = pk(bh, bh);
#pragma unroll
        for (int rp = 0; rp < 8; rp++) { xL[rp] = bl2; xH[rp] = bh2; }
    }
#pragma unroll 4
    for (int j = 0; j < 64; j++) {
        ull wp = we2[j * 32 + lane];
        float wl, wh;
        upk(wp, wl, wh);
        ull wl2 = pk(wl, wl), wh2 = pk(wh, wh);
        const ull* s = S + j * 9;
#pragma unroll
        for (int rp = 0; rp < 8; rp++) {
            ull s2 = s[rp];
            xL[rp] = f2fma(s2, wl2, xL[rp]);
            xH[rp] = f2fma(s2, wh2, xH[rp]);
        }
    }
    __syncwarp();
#pragma unroll
    for (int rp = 0; rp < 8; rp++) {
        S[lane * 9 + rp]        = xL[rp];
        S[(lane + 32) * 9 + rp] = xH[rp];
    }
    __syncwarp();

    ull qL[8], qH[8], kL[8], kH[8], vL[8], vH[8];
#pragma unroll
    for (int rp = 0; rp < 8; rp++) {
        qL[rp] = qH[rp] = kL[rp] = kH[rp] = vL[rp] = vH[rp] = 0ull;
    }
#pragma unroll 2
    for (int j = 0; j < 64; j++) {
        float a, b;
        upk(wq2[j * 32 + lane], a, b);
        ull wql = pk(a, a), wqh = pk(b, b);
        upk(wk2[j * 32 + lane], a, b);
        ull wkl = pk(a, a), wkh = pk(b, b);
        upk(wv2[j * 32 + lane], a, b);
        ull wvl = pk(a, a), wvh = pk(b, b);
        const ull* s = S + j * 9;
#pragma unroll
        for (int rp = 0; rp < 8; rp++) {
            ull s2 = s[rp];
            qL[rp] = f2fma(s2, wql, qL[rp]);
            qH[rp] = f2fma(s2, wqh, qH[rp]);
            kL[rp] = f2fma(s2, wkl, kL[rp]);
            kH[rp] = f2fma(s2, wkh, kH[rp]);
            vL[rp] = f2fma(s2, wvl, vL[rp]);
            vH[rp] = f2fma(s2, wvh, vH[rp]);
        }
    }

#pragma unroll
    for (int rp = 0; rp < 8; rp++) {
        size_t r0 = (size_t)(rows + 2 * rp) * 32 + lane;
        size_t r1 = r0 + 32;
        float a0, a1, b0, b1;
        upk(qL[rp], a0, a1); upk(qH[rp], b0, b1);
        g_q2[r0] = pk(a0, b0); g_q2[r1] = pk(a1, b1);
        upk(kL[rp], a0, a1); upk(kH[rp], b0, b1);
        g_k2[r0] = pk(a0, b0); g_k2[r1] = pk(a1, b1);
        upk(vL[rp], a0, a1); upk(vH[rp], b0, b1);
        g_v2[r0] = pk(a0, b0); g_v2[r1] = pk(a1, b1);
    }
}

// ---------------------------------------------------------------------------
// Kernel 2: KNN — radius-band pruned scan over binned points (validated R12
// structure; bounds now exact per-tile min/max). Selection machinery
// byte-identical to R9.
// ---------------------------------------------------------------------------
#define FSLOTS 64

__device__ __noinline__ void knn_flush(ull* kd, int& bc, float& theta, int lane) {
    int n = 16 + bc;
    ull k0 = (lane < n) ? kd[lane] : ~0ull;
    ull k1 = (lane + 32 < n) ? kd[lane + 32] : ~0ull;
    int r0 = 0, r1 = 0;
    for (int j = 0; j < n; j++) {
        ull kj = kd[j];
        r0 += (kj < k0);
        r1 += (kj < k1);
    }
    __syncwarp();
    if (r0 < 16) kd[r0] = k0;
    if (r1 < 16) kd[r1] = k1;
    __syncwarp();
    unsigned hi = (unsigned)(kd[15] >> 32);
    unsigned u = (hi & 0x80000000u) ? (hi ^ 0x80000000u) : ~hi;
    theta = __uint_as_float(u);
    bc = 0;
}

__global__ void __launch_bounds__(256) knn_kernel() {
    extern __shared__ ull ku[];
    float4* tile = (float4*)ku;                 // TS float4 = 512 ull
    ull*    kbuf = ku + 512;                    // 16*64 = 1024 ull
    int*    tidx = (int*)(ku + 1536);           // TS ints = 128 ull
    int*    flg  = (int*)(ku + 1536 + 128);     // 2 ints

    int tid = threadIdx.x, lane = tid & 31, w = tid >> 5;
    int b = blockIdx.y;
    int p0 = blockIdx.x * QPB + 2 * w;
    int p1 = p0 + 1;
    const float4* sp = s_pos4g + (size_t)b * NN;
    const int*   soi = s_oidxg + (size_t)b * NN;
    float4 qv0 = sp[p0], qv1 = sp[p1];
    float rq0 = sqrtf(qv0.w), rq1 = sqrtf(qv1.w);
    int oq0 = soi[p0], oq1 = soi[p1];

    ull* kd0 = kbuf + (w * 2 + 0) * FSLOTS;
    ull* kd1 = kbuf + (w * 2 + 1) * FSLOTS;
    if (lane < 16) {
        kd0[lane] = (((ull)0xFF7FFFFFu) << 32) | (unsigned)lane;
        kd1[lane] = (((ull)0xFF7FFFFFu) << 32) | (unsigned)lane;
    }
    __syncwarp();

    float th0 = FLT_MAX, th1 = FLT_MAX;
    int bc0 = 0, bc1 = 0;
    int h = (blockIdx.x * QPB) / TS;

    // ---- home tile: load, prime theta from first 32, scan the rest ----
    for (int i = tid; i < TS; i += 256) {
        tile[i] = sp[h * TS + i];
        tidx[i] = soi[h * TS + i];
    }
    __syncthreads();
    {
        float4 c = tile[lane];
        float dot0 = fmaf(qv0.z, c.z, fmaf(qv0.y, c.y, qv0.x * c.x));
        float dot1 = fmaf(qv1.z, c.z, fmaf(qv1.y, c.y, qv1.x * c.x));
        float d20 = fmaf(-2.f, dot0, qv0.w + c.w);
        float d21 = fmaf(-2.f, dot1, qv1.w + c.w);
        int oi = tidx[lane];
        kd0[16 + lane] = (((ull)senc(d20)) << 32) | (unsigned)oi;
        kd1[16 + lane] = (((ull)senc(d21)) << 32) | (unsigned)oi;
        __syncwarp();
        bc0 = 32; knn_flush(kd0, bc0, th0, lane);
        bc1 = 32; knn_flush(kd1, bc1, th1, lane);
    }
    for (int s = 1; s < TS / 32; s++) {
        float4 c = tile[s * 32 + lane];
        float dot0 = fmaf(qv0.z, c.z, fmaf(qv0.y, c.y, qv0.x * c.x));
        float dot1 = fmaf(qv1.z, c.z, fmaf(qv1.y, c.y, qv1.x * c.x));
        float d20 = fmaf(-2.f, dot0, qv0.w + c.w);
        float d21 = fmaf(-2.f, dot1, qv1.w + c.w);
        bool a0 = d20 < th0;
        bool a1 = d21 < th1;
        if (__ballot_sync(0xffffffffu, a0 | a1)) {
            if (bc0 > 16) { knn_flush(kd0, bc0, th0, lane); a0 = d20 < th0; }
            if (bc1 > 16) { knn_flush(kd1, bc1, th1, lane); a1 = d21 < th1; }
            unsigned m0 = __ballot_sync(0xffffffffu, a0);
            unsigned m1 = __ballot_sync(0xffffffffu, a1);
            int oi = tidx[s * 32 + lane];
            if (m0) {
                int off = __popc(m0 & ((1u << lane) - 1u));
                if (a0) kd0[16 + bc0 + off] = (((ull)senc(d20)) << 32) | (unsigned)oi;
                bc0 += __popc(m0);
            }
            if (m1) {
                int off = __popc(m1 & ((1u << lane) - 1u));
                if (a1) kd1[16 + bc1 + off] = (((ull)senc(d21)) << 32) | (unsigned)oi;
                bc1 += __popc(m1);
            }
        }
    }

    // ---- outward expansion with radius-gap termination (exact bounds) ----
    int lo = h, hi = h, toggle = 0;
    while (true) {
        bool ndn = false, nup = false;
        if (lo > 0) {
            float rb = g_maxbelow[b][lo];   // max radius among unscanned below
            float g0 = rq0 - rb, g1 = rq1 - rb;
            if (!(g0 > 0.f && g0 * g0 >= th0 * 1.0001f)) ndn = true;
            if (!(g1 > 0.f && g1 * g1 >= th1 * 1.0001f)) ndn = true;
        }
        if (hi < NT - 1) {
            float ra = g_minabove[b][hi + 1];  // min radius among unscanned above
            float g0 = ra - rq0, g1 = ra - rq1;
            if (!(g0 > 0.f && g0 * g0 >= th0 * 1.0001f)) nup = true;
            if (!(g1 > 0.f && g1 * g1 >= th1 * 1.0001f)) nup = true;
        }
        __syncthreads();
        if (tid < 2) flg[tid] = 0;
        __syncthreads();
        if (lane == 0) {
            if (ndn) atomicOr(&flg[0], 1);
            if (nup) atomicOr(&flg[1], 1);
        }
        __syncthreads();
        int fdn = flg[0], fup = flg[1];
        if (!fdn && !fup) break;
        int t;
        if (fup && (!fdn || toggle == 0)) { t = ++hi; toggle = 1; }
        else                              { t = --lo; toggle = 0; }

        for (int i = tid; i < TS; i += 256) {
            tile[i] = sp[t * TS + i];
            tidx[i] = soi[t * TS + i];
        }
        __syncthreads();
        for (int s = 0; s < TS / 32; s++) {
            float4 c = tile[s * 32 + lane];
            float dot0 = fmaf(qv0.z, c.z, fmaf(qv0.y, c.y, qv0.x * c.x));
            float dot1 = fmaf(qv1.z, c.z, fmaf(qv1.y, c.y, qv1.x * c.x));
            float d20 = fmaf(-2.f, dot0, qv0.w + c.w);
            float d21 = fmaf(-2.f, dot1, qv1.w + c.w);
            bool a0 = d20 < th0;
            bool a1 = d21 < th1;
            if (__ballot_sync(0xffffffffu, a0 | a1)) {
                if (bc0 > 16) { knn_flush(kd0, bc0, th0, lane); a0 = d20 < th0; }
                if (bc1 > 16) { knn_flush(kd1, bc1, th1, lane); a1 = d21 < th1; }
                unsigned m0 = __ballot_sync(0xffffffffu, a0);
                unsigned m1 = __ballot_sync(0xffffffffu, a1);
                int oi = tidx[s * 32 + lane];
                if (m0) {
                    int off = __popc(m0 & ((1u << lane) - 1u));
                    if (a0) kd0[16 + bc0 + off] = (((ull)senc(d20)) << 32) | (unsigned)oi;
                    bc0 += __popc(m0);
                }
                if (m1) {
                    int off = __popc(m1 & ((1u << lane) - 1u));
                    if (a1) kd1[16 + bc1 + off] = (((ull)senc(d21)) << 32) | (unsigned)oi;
                    bc1 += __popc(m1);
                }
            }
        }
    }
    if (bc0 > 0) knn_flush(kd0, bc0, th0, lane);
    if (bc1 > 0) knn_flush(kd1, bc1, th1, lane);
    if (lane < 16) {
        g_idx[((size_t)b * NN + oq0) * KK + lane] = (int)(unsigned)(kd0[lane] & 0xFFFFFFFFu);
        g_idx[((size_t)b * NN + oq1) * KK + lane] = (int)(unsigned)(kd1[lane] & 0xFFFFFFFFu);
    }
}

// ---------------------------------------------------------------------------
// Kernel 3: fused posenc + attn MLPs + softmax + combine + out projection.
// (exact R9 version: AQ=8, smem ulonglong2 weights; measured 165-166 us)
// ---------------------------------------------------------------------------
#define AQ 8
#define SQSTRIDE 640

__device__ __forceinline__ void mv16x64(const ull* __restrict__ Sq,
                                        const ulonglong2* __restrict__ w4, int l,
                                        ull aL[8], ull aH[8]) {
#pragma unroll
    for (int kp = 0; kp < 8; kp++) { aL[kp] = 0ull; aH[kp] = 0ull; }
#pragma unroll 4
    for (int jp = 0; jp < 32; jp++) {
        ulonglong2 wpp = w4[jp * 32 + l];
        {
            float wl, wh;
            upk(wpp.x, wl, wh);
            ull wl2 = pk(wl, wl), wh2 = pk(wh, wh);
            const ulonglong2* s = (const ulonglong2*)(Sq + (2 * jp) * 10);
#pragma unroll
            for (int kp2 = 0; kp2 < 4; kp2++) {
                ulonglong2 sv = s[kp2];
                aL[2 * kp2]     = f2fma(sv.x, wl2, aL[2 * kp2]);
                aH[2 * kp2]     = f2fma(sv.x, wh2, aH[2 * kp2]);
                aL[2 * kp2 + 1] = f2fma(sv.y, wl2, aL[2 * kp2 + 1]);
                aH[2 * kp2 + 1] = f2fma(sv.y, wh2, aH[2 * kp2 + 1]);
            }
        }
        {
            float wl, wh;
            upk(wpp.y, wl, wh);
            ull wl2 = pk(wl, wl), wh2 = pk(wh, wh);
            const ulonglong2* s = (const ulonglong2*)(Sq + (2 * jp + 1) * 10);
#pragma unroll
            for (int kp2 = 0; kp2 < 4; kp2++) {
                ulonglong2 sv = s[kp2];
                aL[2 * kp2]     = f2fma(sv.x, wl2, aL[2 * kp2]);
                aH[2 * kp2]     = f2fma(sv.x, wh2, aH[2 * kp2]);
                aL[2 * kp2 + 1] = f2fma(sv.y, wl2, aL[2 * kp2 + 1]);
                aH[2 * kp2 + 1] = f2fma(sv.y, wh2, aH[2 * kp2 + 1]);
            }
        }
    }
}

__global__ void __launch_bounds__(256) attn_kernel(
        const float* __restrict__ feat,
        const float* __restrict__ pe_w1, const float* __restrict__ pe_b1,
        const float* __restrict__ pe_w2, const float* __restrict__ pe_b2,
        const float* __restrict__ at_w1, const float* __restrict__ at_b1,
        const float* __restrict__ at_w2, const float* __restrict__ at_b2,
        const float* __restrict__ out_w, const float* __restrict__ out_b,
        float* __restrict__ out) {
    extern __shared__ ull smu[];
    ulonglong2* w4_pe2 = (ulonglong2*)smu;           // 1024 u2 (2048 ull)
    ulonglong2* w4_at1 = (ulonglong2*)(smu + 2048);
    ulonglong2* w4_at2 = (ulonglong2*)(smu + 4096);
    ull* Sp2    = smu + 6144;            // AQ*640
    float* s_pe1 = (float*)(Sp2 + AQ * SQSTRIDE);  // 192
    float* s_b   = s_pe1 + 192;          // 320
    float* relb  = s_b + 320;            // AQ*64
    float* resb  = relb + AQ * 64;       // AQ*64
    int*   idxb  = (int*)(resb + AQ * 64);  // AQ*16

    int tid = threadIdx.x;
    for (int e = tid; e < 1024; e += 256) {
        int jp = e >> 5, l2 = e & 31;
        int j0 = 2 * jp, j1 = 2 * jp + 1;
        w4_pe2[e] = make_ulonglong2(pk(pe_w2[j0 * 64 + l2], pe_w2[j0 * 64 + l2 + 32]),
                                    pk(pe_w2[j1 * 64 + l2], pe_w2[j1 * 64 + l2 + 32]));
        w4_at1[e] = make_ulonglong2(pk(at_w1[j0 * 64 + l2], at_w1[j0 * 64 + l2 + 32]),
                                    pk(at_w1[j1 * 64 + l2], at_w1[j1 * 64 + l2 + 32]));
        w4_at2[e] = make_ulonglong2(pk(at_w2[j0 * 64 + l2], at_w2[j0 * 64 + l2 + 32]),
                                    pk(at_w2[j1 * 64 + l2], at_w2[j1 * 64 + l2 + 32]));
    }
    if (tid < 192) s_pe1[tid] = pe_w1[tid];
    if (tid < 64) {
        s_b[tid]       = pe_b1[tid];
        s_b[64 + tid]  = pe_b2[tid];
        s_b[128 + tid] = at_b1[tid];
        s_b[192 + tid] = at_b2[tid];
        s_b[256 + tid] = out_b[tid];
    }

    int wid = tid >> 5;
    int l   = tid & 31;
    int g   = blockIdx.x * AQ + wid;
    int bbase = g & ~(NN - 1);

    float q_lo, q_hi;
    upk(g_q2[(size_t)g * 32 + l], q_lo, q_hi);

    if (l < KK) {
        int ii = g_idx[(size_t)g * KK + l];
        idxb[wid * KK + l] = ii;
        float4 np = g_pos4[bbase + ii];
        float4 qp = g_pos4[g];
        relb[(wid * KK + l) * 4 + 0] = np.x - qp.x;
        relb[(wid * KK + l) * 4 + 1] = np.y - qp.y;
        relb[(wid * KK + l) * 4 + 2] = np.z - qp.z;
    }
    __syncthreads();

    ull* Sq = Sp2 + wid * SQSTRIDE;

    // Stage A: pe1 = relu(rel @ pe_w1 + pe_b1)
    {
        float w0l = s_pe1[l],      w1l = s_pe1[64 + l],  w2l = s_pe1[128 + l];
        float w0h = s_pe1[l + 32], w1h = s_pe1[96 + l],  w2h = s_pe1[160 + l];
        float b1l = s_b[l], b1h = s_b[l + 32];
#pragma unroll
        for (int kp = 0; kp < 8; kp++) {
            const float* ra = relb + (wid * KK + 2 * kp) * 4;
            const float* rb = ra + 4;
            float pa = fmaxf(fmaf(ra[2], w2l, fmaf(ra[1], w1l, fmaf(ra[0], w0l, b1l))), 0.f);
            float pb = fmaxf(fmaf(rb[2], w2l, fmaf(rb[1], w1l, fmaf(rb[0], w0l, b1l))), 0.f);
            Sq[l * 10 + kp] = pk(pa, pb);
            float qa = fmaxf(fmaf(ra[2], w2h, fmaf(ra[1], w1h, fmaf(ra[0], w0h, b1h))), 0.f);
            float qb = fmaxf(fmaf(rb[2], w2h, fmaf(rb[1], w1h, fmaf(rb[0], w0h, b1h))), 0.f);
            Sq[(l + 32) * 10 + kp] = pk(qa, qb);
        }
    }
    __syncwarp();

    // Stage B: posenc = pe1 @ pe_w2 + pe_b2
    ull penL[8], penH[8];
    mv16x64(Sq, w4_pe2, l, penL, penH);
    {
        ull b2l = pk(s_b[64 + l], s_b[64 + l]);
        ull b2h = pk(s_b[64 + l + 32], s_b[64 + l + 32]);
#pragma unroll
        for (int kp = 0; kp < 8; kp++) {
            penL[kp] = f2add(penL[kp], b2l);
            penH[kp] = f2add(penH[kp], b2h);
        }
    }
    __syncwarp();

    // Stage C: h = q - k_feat + posenc
#pragma unroll
    for (int kp = 0; kp < 8; kp++) {
        int i0 = idxb[wid * KK + 2 * kp];
        int i1 = idxb[wid * KK + 2 * kp + 1];
        float k0l, k0h, k1l, k1h;
        upk(g_k2[(size_t)(bbase + i0) * 32 + l], k0l, k0h);
        upk(g_k2[(size_t)(bbase + i1) * 32 + l], k1l, k1h);
        float p0, p1;
        upk(penL[kp], p0, p1);
        Sq[l * 10 + kp] = pk(q_lo - k0l + p0, q_lo - k1l + p1);
        upk(penH[kp], p0, p1);
        Sq[(l + 32) * 10 + kp] = pk(q_hi - k0h + p0, q_hi - k1h + p1);
    }
    __syncwarp();

    // Stage D: a1 = relu(h @ at_w1 + at_b1)
    ull aL[8], aH[8];
    mv16x64(Sq, w4_at1, l, aL, aH);
    __syncwarp();
    {
        float bl = s_b[128 + l], bh = s_b[128 + l + 32];
#pragma unroll
        for (int kp = 0; kp < 8; kp++) {
            float x, y;
            upk(aL[kp], x, y);
            Sq[l * 10 + kp] = pk(fmaxf(x + bl, 0.f), fmaxf(y + bl, 0.f));
            upk(aH[kp], x, y);
            Sq[(l + 32) * 10 + kp] = pk(fmaxf(x + bh, 0.f), fmaxf(y + bh, 0.f));
        }
    }
    __syncwarp();

    // Stage E: logits = (a1 @ at_w2 + at_b2) / 8
    mv16x64(Sq, w4_at2, l, aL, aH);
    float el[KK], eh[KK];
    {
        float bl = s_b[192 + l], bh = s_b[192 + l + 32];
#pragma unroll
        for (int kp = 0; kp < 8; kp++) {
            float x, y;
            upk(aL[kp], x, y);
            el[2 * kp] = (x + bl) * 0.125f; el[2 * kp + 1] = (y + bl) * 0.125f;
            upk(aH[kp], x, y);
            eh[2 * kp] = (x + bh) * 0.125f; eh[2 * kp + 1] = (y + bh) * 0.125f;
        }
    }

    // softmax over K per channel + combine with (v + posenc)
    float ml = el[0], mh = eh[0];
#pragma unroll
    for (int k = 1; k < KK; k++) { ml = fmaxf(ml, el[k]); mh = fmaxf(mh, eh[k]); }
    float sl = 0.f, sh = 0.f;
#pragma unroll
    for (int k = 0; k < KK; k++) {
        el[k] = __expf(el[k] - ml); sl += el[k];
        eh[k] = __expf(eh[k] - mh); sh += eh[k];
    }
    float il = 1.f / sl, ih = 1.f / sh;
    float res_lo = 0.f, res_hi = 0.f;
#pragma unroll
    for (int kp = 0; kp < 8; kp++) {
        int i0 = idxb[wid * KK + 2 * kp];
        int i1 = idxb[wid * KK + 2 * kp + 1];
        float v0l, v0h, v1l, v1h;
        upk(g_v2[(size_t)(bbase + i0) * 32 + l], v0l, v0h);
        upk(g_v2[(size_t)(bbase + i1) * 32 + l], v1l, v1h);
        float p0, p1;
        upk(penL[kp], p0, p1);
        res_lo = fmaf(el[2 * kp] * il,     v0l + p0, res_lo);
        res_lo = fmaf(el[2 * kp + 1] * il, v1l + p1, res_lo);
        upk(penH[kp], p0, p1);
        res_hi = fmaf(eh[2 * kp] * ih,     v0h + p0, res_hi);
        res_hi = fmaf(eh[2 * kp + 1] * ih, v1h + p1, res_hi);
    }
    resb[wid * CC + l] = res_lo;
    resb[wid * CC + l + 32] = res_hi;
    __syncwarp();

    // final: out = res @ out_w + out_b + features (out_w via L1)
    {
        float ol = s_b[256 + l], oh = s_b[256 + l + 32];
#pragma unroll 4
        for (int j = 0; j < 64; j++) {
            float rj = resb[wid * CC + j];
            ol = fmaf(rj, __ldg(&out_w[j * 64 + l]), ol);
            oh = fmaf(rj, __ldg(&out_w[j * 64 + l + 32]), oh);
        }
        out[(size_t)g * CC + l]      = ol + feat[(size_t)g * CC + l];
        out[(size_t)g * CC + l + 32] = oh + feat[(size_t)g * CC + l + 32];
    }
}

// ---------------------------------------------------------------------------
extern "C" void kernel_launch(void* const* d_in, const int* in_sizes, int n_in,
                              void* d_out, int out_size) {
    const float* pos   = (const float*)d_in[0];
    const float* feat  = (const float*)d_in[1];
    const float* emb_w = (const float*)d_in[2];
    const float* emb_b = (const float*)d_in[3];
    const float* wq    = (const float*)d_in[4];
    const float* wk    = (const float*)d_in[5];
    const float* wv    = (const float*)d_in[6];
    const float* pe_w1 = (const float*)d_in[7];
    const float* pe_b1 = (const float*)d_in[8];
    const float* pe_w2 = (const float*)d_in[9];
    const float* pe_b2 = (const float*)d_in[10];
    const float* at_w1 = (const float*)d_in[11];
    const float* at_b1 = (const float*)d_in[12];
    const float* at_w2 = (const float*)d_in[13];
    const float* at_b2 = (const float*)d_in[14];
    const float* out_w = (const float*)d_in[15];
    const float* out_b = (const float*)d_in[16];
    float* out = (float*)d_out;

    int proj_smem = (8192 + PW * 576 + 32) * 8;
    int knn_smem  = (512 + 1024 + 128 + 1) * 8;
    int attn_smem = (6144 + AQ * SQSTRIDE) * 8
                  + (192 + 320 + AQ * 64 * 2) * 4 + AQ * KK * 4;
    cudaFuncSetAttribute(proj_kernel, cudaFuncAttributeMaxDynamicSharedMemorySize, proj_smem);
    cudaFuncSetAttribute(knn_kernel, cudaFuncAttributeMaxDynamicSharedMemorySize, knn_smem);
    cudaFuncSetAttribute(attn_kernel, cudaFuncAttributeMaxDynamicSharedMemorySize, attn_smem);

    init_kernel<<<BB, NBINS>>>();
    prep_kernel<<<BN / 256, 256>>>(pos);
    hist_kernel<<<BN / 256, 256>>>();
    scan_kernel<<<BB, NBINS>>>();
    scatter_kernel<<<BN / 256, 256>>>();
    bounds_kernel<<<BB, 1024>>>();
    proj_kernel<<<BN / (PW * 16), 128, proj_smem>>>(feat, emb_w, emb_b, wq, wk, wv);
    knn_kernel<<<dim3(NN / QPB, BB), 256, knn_smem>>>();
    attn_kernel<<<BN / AQ, 256, attn_smem>>>(feat, pe_w1, pe_b1, pe_w2, pe_b2,
                                             at_w1, at_b1, at_w2, at_b2, out_w, out_b, out);
}